// round 12
// baseline (speedup 1.0000x reference)
#include <cuda_runtime.h>
#include <cstdint>

#define NUM_USER   4096
#define NUM_ITEM   16384
#define NUM_HIDDEN 64
#define BATCH      1024
#define SETLEN     50
#define NJ         (BATCH * SETLEN)              // 51200 scatter updates

#define PLANE      ((size_t)NUM_USER * NUM_ITEM) // 67,108,864 cells per plane
#define LPJ        8                             // lanes per update in resolve

#define TAG_BLOCKS  200                          // 200*256 = 51200 tag threads
#define FILL_BLOCKS 2048                         // pred-plane fill blocks
#define K2_GRID     (TAG_BLOCKS + FILL_BLOCKS)
#define N_FLOAT4    (PLANE / 4)                  // 16,777,216 float4 in a plane

// Only persistent device state. INVARIANT: zero at the start of every
// launch / graph replay (resolve_kernel resets it after use).
__device__ unsigned int g_nnz;

// ---------------------------------------------------------------------------
// k2: fused tag + pred-plane fill. Block roles:
//   blocks [0, TAG_BLOCKS):    arbitration — thread j tags label[cell] with
//     j+1 via atomicMax (surviving tag = max j = last-write-wins in (b,l)
//     row-major order, XLA scatter semantics). First toucher (old==0, label
//     plane zeroed by the preceding memset) counts the unique cell.
//   blocks [TAG_BLOCKS, ...):  coalesced float4 zero-fill of the PRED plane.
// The two roles touch disjoint planes -> no intra-kernel ordering needed;
// tag's ~4us hides entirely under the ~40us DRAM-bound fill.
// ---------------------------------------------------------------------------
__global__ void __launch_bounds__(256)
tag_fill_kernel(const int* __restrict__ idx_user,
                const int* __restrict__ item_sets,
                float* __restrict__ out) {
    if (blockIdx.x < TAG_BLOCKS) {
        int j = blockIdx.x * blockDim.x + threadIdx.x;   // < NJ exactly
        int b = j / SETLEN;
        unsigned int u    = (unsigned int)__ldg(idx_user + b);
        unsigned int it   = (unsigned int)__ldg(item_sets + j);
        unsigned int cell = u * NUM_ITEM + it;

        int old = atomicMax((int*)(out + PLANE) + cell, j + 1);
        if (old == 0) atomicAdd(&g_nnz, 1u);
    } else {
        // Pred-plane zero fill: fully coalesced 16B stores, grid-stride.
        float4  z = make_float4(0.f, 0.f, 0.f, 0.f);
        float4* p = (float4*)out;
        size_t  i = (size_t)(blockIdx.x - TAG_BLOCKS) * blockDim.x + threadIdx.x;
        const size_t stride = (size_t)FILL_BLOCKS * 256;
        for (; i < N_FLOAT4; i += stride) p[i] = z;
    }
}

// ---------------------------------------------------------------------------
// k3: warp-split resolve (R10-proven, 7.5us). 8 lanes per update j:
//  - each lane loads 8 dims (2 float4 pairs), butterfly shuffle-reduce.
//  - pred: stored unconditionally by lane 0 — duplicates of a cell share
//    (u, it) => identical dot, so the race writes identical bits (benign).
//  - label: lane 0 loads the tag early (independent of embed loads); the
//    unique winner (tag == j+1) overwrites the tag with its rating.
//  - global thread 0 emits sparsity and restores g_nnz = 0.
// ---------------------------------------------------------------------------
__global__ void resolve_kernel(const int*   __restrict__ idx_user,
                               const int*   __restrict__ item_sets,
                               const float* __restrict__ ratings,
                               const float* __restrict__ embed_user,
                               const float* __restrict__ embed_item,
                               float* __restrict__ out) {
    int t = blockIdx.x * blockDim.x + threadIdx.x;
    if (t == 0) {
        out[2 * PLANE] = (float)((double)PLANE / (double)g_nnz);
        g_nnz = 0u;                              // self-cleaning invariant
    }
    int j = t >> 3;                              // update index
    int r = t & (LPJ - 1);                       // lane within 8-group
    if (j >= NJ) return;

    int b = j / SETLEN;
    unsigned int u    = (unsigned int)__ldg(idx_user + b);
    unsigned int it   = (unsigned int)__ldg(item_sets + j);
    unsigned int cell = u * NUM_ITEM + it;

    // Lane 0 issues the scattered tag + rating loads up front, overlapped
    // with everyone's embed loads (all independent addresses).
    int   tag = 0;
    float rat = 0.f;
    if (r == 0) {
        tag = ((const int*)(out + PLANE))[cell];
        rat = __ldg(ratings + j);
    }

    // Each lane: 8 dims = 2 float4 pairs, 8 FMAs.
    const float4* ur = (const float4*)(embed_user + (size_t)u  * NUM_HIDDEN);
    const float4* ir = (const float4*)(embed_item + (size_t)it * NUM_HIDDEN);
    float4 a0 = ur[2*r+0], c0 = ir[2*r+0];
    float4 a1 = ur[2*r+1], c1 = ir[2*r+1];
    float s  = fmaf(a0.x,c0.x, fmaf(a0.y,c0.y, fmaf(a0.z,c0.z, a0.w*c0.w)));
    s       += fmaf(a1.x,c1.x, fmaf(a1.y,c1.y, fmaf(a1.z,c1.z, a1.w*c1.w)));

    // Butterfly reduce within the 8-lane group.
    s += __shfl_xor_sync(0xFFFFFFFFu, s, 4, LPJ);
    s += __shfl_xor_sync(0xFFFFFFFFu, s, 2, LPJ);
    s += __shfl_xor_sync(0xFFFFFFFFu, s, 1, LPJ);

    if (r == 0) {
        out[cell] = s;                           // pred: benign identical race
        if (tag == j + 1)
            out[PLANE + cell] = rat;             // label: unique winner
    }
}

// ---------------------------------------------------------------------------
// Pipeline: memset(label, 256MB) -> fused [tag || fill(pred, 256MB)] ->
// warp-split resolve. Tag's latency-bound work hides under the DRAM-bound
// pred fill inside ONE kernel (block specialization — scheduler-proof,
// unlike the failed cross-stream overlap of R5).
// ---------------------------------------------------------------------------
extern "C" void kernel_launch(void* const* d_in, const int* in_sizes, int n_in,
                              void* d_out, int out_size) {
    const int*   idx_user   = (const int*)  d_in[0];
    const int*   item_sets  = (const int*)  d_in[1];
    const float* rating     = (const float*)d_in[2];
    const float* embed_user = (const float*)d_in[3];
    const float* embed_item = (const float*)d_in[4];
    float* out = (float*)d_out;

    // Zero the LABEL plane only (tag needs it; pred is filled in k2).
    cudaMemsetAsync(out + PLANE, 0, PLANE * sizeof(float), 0);
    tag_fill_kernel<<<K2_GRID, 256>>>(idx_user, item_sets, out);
    resolve_kernel <<<(NJ * LPJ + 255) / 256, 256>>>(idx_user, item_sets, rating,
                                                     embed_user, embed_item, out);
}

// round 13
// speedup vs baseline: 1.0419x; 1.0419x over previous
#include <cuda_runtime.h>
#include <cstdint>

#define NUM_USER   4096
#define NUM_ITEM   16384
#define NUM_HIDDEN 64
#define BATCH      1024
#define SETLEN     50
#define NJ         (BATCH * SETLEN)              // 51200 scatter updates

#define PLANE      ((size_t)NUM_USER * NUM_ITEM) // 67,108,864 cells per plane
#define LPJ        8                             // lanes per update in resolve

#define TAGB       200                           // tag blocks: 200*256 = NJ
#define RESB       1600                          // resolve blocks: NJ*LPJ/256
#define GRID       (TAGB + RESB)

// Persistent device state. INVARIANT: zero at the start of every launch /
// graph replay — the last resolve block restores all of it.
__device__ unsigned int g_nnz;                   // unique-cell count
__device__ unsigned int g_tagdone;               // tag blocks completed
__device__ unsigned int g_resdone;               // resolve blocks completed

// ---------------------------------------------------------------------------
// ONE kernel, two block roles (tag's 4.2us + a launch gap now hide under
// resolve's tag-independent phase instead of preceding it):
//
//  blocks [0, TAGB): TAG. Thread j atomicMax's label[cell] = j+1 ->
//    surviving tag = max j = last-write-wins in (b,l) row-major order (XLA
//    scatter semantics). First toucher (old==0; label plane zeroed by the
//    preceding memset) counts the unique cell (warp-ballot aggregated).
//    Block then releases g_tagdone. Lowest blockIdx => guaranteed wave-1
//    residency (CTA dispatch is in bid order), so spinners can't starve it.
//
//  blocks [TAGB, GRID): RESOLVE (R10-proven 8-lane split).
//    Pre-barrier (tag-independent): embed loads, butterfly-reduced dot,
//    UNCONDITIONAL pred store (duplicates share (u,it) => identical bits,
//    benign race), rating load.
//    Barrier: thread 0 spins until g_tagdone == TAGB, __syncthreads.
//    Post-barrier: lane 0 reads the final tag; the unique winner (tag==j+1)
//    overwrites the tag with its rating. Block TAGB thread 0 emits the
//    sparsity scalar. The last resolve block resets all counters.
// ---------------------------------------------------------------------------
__global__ void __launch_bounds__(256)
fused_kernel(const int*   __restrict__ idx_user,
             const int*   __restrict__ item_sets,
             const float* __restrict__ ratings,
             const float* __restrict__ embed_user,
             const float* __restrict__ embed_item,
             float* __restrict__ out) {
    const int tid = threadIdx.x;

    if (blockIdx.x < TAGB) {
        // ---------------- TAG role ----------------
        int j = blockIdx.x * 256 + tid;              // < NJ exactly
        int b = j / SETLEN;
        unsigned int u    = (unsigned int)__ldg(idx_user + b);
        unsigned int it   = (unsigned int)__ldg(item_sets + j);
        unsigned int cell = u * NUM_ITEM + it;

        int old = atomicMax((int*)(out + PLANE) + cell, j + 1);

        unsigned int m = __ballot_sync(0xFFFFFFFFu, old == 0);
        if ((tid & 31) == 0 && m) atomicAdd(&g_nnz, __popc(m));

        __syncthreads();
        if (tid == 0) {
            __threadfence();                         // release tags + nnz
            atomicAdd(&g_tagdone, 1u);
        }
        return;
    }

    // ---------------- RESOLVE role ----------------
    int t = (blockIdx.x - TAGB) * 256 + tid;
    int j = t >> 3;                                  // < NJ exactly
    int r = t & (LPJ - 1);

    int b = j / SETLEN;
    unsigned int u    = (unsigned int)__ldg(idx_user + b);
    unsigned int it   = (unsigned int)__ldg(item_sets + j);
    unsigned int cell = u * NUM_ITEM + it;

    float rat = (r == 0) ? __ldg(ratings + j) : 0.f; // tag-independent

    // Each lane: 8 dims = 2 float4 pairs, 8 FMAs.
    const float4* ur = (const float4*)(embed_user + (size_t)u  * NUM_HIDDEN);
    const float4* ir = (const float4*)(embed_item + (size_t)it * NUM_HIDDEN);
    float4 a0 = ur[2*r+0], c0 = ir[2*r+0];
    float4 a1 = ur[2*r+1], c1 = ir[2*r+1];
    float s  = fmaf(a0.x,c0.x, fmaf(a0.y,c0.y, fmaf(a0.z,c0.z, a0.w*c0.w)));
    s       += fmaf(a1.x,c1.x, fmaf(a1.y,c1.y, fmaf(a1.z,c1.z, a1.w*c1.w)));

    s += __shfl_xor_sync(0xFFFFFFFFu, s, 4, LPJ);
    s += __shfl_xor_sync(0xFFFFFFFFu, s, 2, LPJ);
    s += __shfl_xor_sync(0xFFFFFFFFu, s, 1, LPJ);

    if (r == 0) out[cell] = s;                       // pred: before barrier OK
                                                     // (disjoint from tag plane)

    // -------- device-side barrier: wait for all tag blocks --------
    if (tid == 0) {
        while (*(volatile unsigned int*)&g_tagdone < TAGB) { }
        __threadfence();                             // acquire
    }
    __syncthreads();

    if (r == 0) {
        int tag = ((const int*)(out + PLANE))[cell]; // final tag
        if (tag == j + 1)
            out[PLANE + cell] = rat;                 // label: unique winner
    }

    if (blockIdx.x == TAGB && tid == 0)              // nnz final post-barrier
        out[2 * PLANE] = (float)((double)PLANE / (double)g_nnz);

    __syncthreads();                                 // block fully done
    if (tid == 0) {
        unsigned int old = atomicAdd(&g_resdone, 1u);
        if (old == RESB - 1) {                       // last resolve block:
            g_tagdone = 0u;                          // restore pristine state
            g_resdone = 0u;
            g_nnz     = 0u;
        }
    }
}

// ---------------------------------------------------------------------------
// 2-node pipeline: 512MB memset (the proven HBM floor — R2/R4/R12 showed
// hand-rolled fills lose 8-20% to it) + one fused tag/resolve kernel.
// ---------------------------------------------------------------------------
extern "C" void kernel_launch(void* const* d_in, const int* in_sizes, int n_in,
                              void* d_out, int out_size) {
    const int*   idx_user   = (const int*)  d_in[0];
    const int*   item_sets  = (const int*)  d_in[1];
    const float* rating     = (const float*)d_in[2];
    const float* embed_user = (const float*)d_in[3];
    const float* embed_item = (const float*)d_in[4];
    float* out = (float*)d_out;

    cudaMemsetAsync(out, 0, 2ull * PLANE * sizeof(float), 0);
    fused_kernel<<<GRID, 256>>>(idx_user, item_sets, rating,
                                embed_user, embed_item, out);
}

// round 14
// speedup vs baseline: 1.0631x; 1.0204x over previous
#include <cuda_runtime.h>
#include <cstdint>

#define NUM_USER   4096
#define NUM_ITEM   16384
#define NUM_HIDDEN 64
#define BATCH      1024
#define SETLEN     50
#define NJ         (BATCH * SETLEN)              // 51200 scatter updates

#define PLANE      ((size_t)NUM_USER * NUM_ITEM) // 67,108,864 cells per plane
#define LPJ        16                            // lanes per update in resolve

// Only persistent device state. INVARIANT: zero at the start of every
// launch / graph replay (resolve_kernel resets it after use).
__device__ unsigned int g_nnz;

// ---------------------------------------------------------------------------
// Pass 1 (tiny): arbitration ONLY. Thread j tags label[cell] with j+1 via
// atomicMax -> surviving tag = max j = last-write-wins in (b,l) row-major
// order (XLA scatter semantics). First toucher (old==0; label plane zeroed
// by the memset) counts the unique cell — warp-ballot aggregated so the hot
// g_nnz counter sees ~1.6k atomics instead of ~49k.
// ---------------------------------------------------------------------------
__global__ void __launch_bounds__(512)
tag_kernel(const int* __restrict__ idx_user,
           const int* __restrict__ item_sets,
           float* __restrict__ out) {
    int j = blockIdx.x * blockDim.x + threadIdx.x;
    if (j >= NJ) return;
    int b = j / SETLEN;
    unsigned int u    = (unsigned int)__ldg(idx_user + b);
    unsigned int it   = (unsigned int)__ldg(item_sets + j);
    unsigned int cell = u * NUM_ITEM + it;

    int old = atomicMax((int*)(out + PLANE) + cell, j + 1);

    unsigned int m = __ballot_sync(0xFFFFFFFFu, old == 0);
    if ((threadIdx.x & 31) == 0 && m) atomicAdd(&g_nnz, __popc(m));
}

// ---------------------------------------------------------------------------
// Pass 2: warp-split resolve, 16 lanes per update j (R9->R10 proved the
// occupancy lever: 1 lane/j = 11.4us @ occ 16%; 8 lanes/j = 7.5us @ occ 75%;
// 16 lanes/j doubles warp cover again and halves per-lane load latency
// exposure; total L2 bytes unchanged).
//  - each lane loads 4 dims (1 float4 per table), 4 FMAs, 4-step butterfly.
//  - pred: stored unconditionally by lane 0 — duplicates of a cell share
//    (u, it) => identical dot, so the race writes identical bits (benign).
//  - label: lane 0 loads the tag early (independent of the embed loads);
//    the unique winner (tag == j+1) overwrites the tag with its rating.
//  - global thread 0 emits sparsity and restores g_nnz = 0.
// ---------------------------------------------------------------------------
__global__ void __launch_bounds__(256)
resolve_kernel(const int*   __restrict__ idx_user,
               const int*   __restrict__ item_sets,
               const float* __restrict__ ratings,
               const float* __restrict__ embed_user,
               const float* __restrict__ embed_item,
               float* __restrict__ out) {
    int t = blockIdx.x * blockDim.x + threadIdx.x;
    if (t == 0) {
        out[2 * PLANE] = (float)((double)PLANE / (double)g_nnz);
        g_nnz = 0u;                              // self-cleaning invariant
    }
    int j = t >> 4;                              // update index
    int r = t & (LPJ - 1);                       // lane within 16-group
    if (j >= NJ) return;

    int b = j / SETLEN;
    unsigned int u    = (unsigned int)__ldg(idx_user + b);
    unsigned int it   = (unsigned int)__ldg(item_sets + j);
    unsigned int cell = u * NUM_ITEM + it;

    // Lane 0 issues the scattered tag + rating loads up front, overlapped
    // with everyone's embed loads (all independent addresses).
    int   tag = 0;
    float rat = 0.f;
    if (r == 0) {
        tag = ((const int*)(out + PLANE))[cell];
        rat = __ldg(ratings + j);
    }

    // Each lane: 4 dims = 1 float4 per table, 4 FMAs.
    const float4* ur = (const float4*)(embed_user + (size_t)u  * NUM_HIDDEN);
    const float4* ir = (const float4*)(embed_item + (size_t)it * NUM_HIDDEN);
    float4 a = ur[r];
    float4 c = ir[r];
    float s = fmaf(a.x, c.x, fmaf(a.y, c.y, fmaf(a.z, c.z, a.w * c.w)));

    // Butterfly reduce within the 16-lane group.
    s += __shfl_xor_sync(0xFFFFFFFFu, s, 8, LPJ);
    s += __shfl_xor_sync(0xFFFFFFFFu, s, 4, LPJ);
    s += __shfl_xor_sync(0xFFFFFFFFu, s, 2, LPJ);
    s += __shfl_xor_sync(0xFFFFFFFFu, s, 1, LPJ);

    if (r == 0) {
        out[cell] = s;                           // pred: benign identical race
        if (tag == j + 1)
            out[PLANE + cell] = rat;             // label: unique winner
    }
}

// ---------------------------------------------------------------------------
// 3-node pipeline (structure proven optimal across R5/R13 overlap attempts
// and R2/R4/R12 fill attempts): 512MB memset (HBM floor, ~80us) ->
// arbitration pass -> 16-lane warp-split resolve.
// ---------------------------------------------------------------------------
extern "C" void kernel_launch(void* const* d_in, const int* in_sizes, int n_in,
                              void* d_out, int out_size) {
    const int*   idx_user   = (const int*)  d_in[0];
    const int*   item_sets  = (const int*)  d_in[1];
    const float* rating     = (const float*)d_in[2];
    const float* embed_user = (const float*)d_in[3];
    const float* embed_item = (const float*)d_in[4];
    float* out = (float*)d_out;

    cudaMemsetAsync(out, 0, 2ull * PLANE * sizeof(float), 0);
    tag_kernel    <<<(NJ + 511) / 512, 512>>>(idx_user, item_sets, out);
    resolve_kernel<<<(NJ * LPJ + 255) / 256, 256>>>(idx_user, item_sets, rating,
                                                    embed_user, embed_item, out);
}

// round 16
// speedup vs baseline: 1.0766x; 1.0127x over previous
#include <cuda_runtime.h>
#include <cstdint>

#define NUM_USER   4096
#define NUM_ITEM   16384
#define NUM_HIDDEN 64
#define BATCH      1024
#define SETLEN     50
#define NJ         (BATCH * SETLEN)              // 51200 scatter updates

#define PLANE      ((size_t)NUM_USER * NUM_ITEM) // 67,108,864 cells per plane
#define LPJ        8                             // lanes per update (R10/R14: optimum)

// Only persistent device state. INVARIANT: zero at the start of every
// launch / graph replay (resolve_kernel resets it after use).
__device__ unsigned int g_nnz;

// 32B load (two float4s) with L2 evict-last policy — the shape ptxas
// requires for this modifier on sm_100a (.v4.b64). Keeps the 5MB embed
// tables L2-resident across replays despite the 512MB memset sweep.
// p must be 32B-aligned (embed rows are 256B-aligned; offsets are 32B).
__device__ __forceinline__ void ldg32B_evict_last(const float4* p,
                                                  float4& v0, float4& v1) {
    unsigned long long x0, x1, x2, x3;
    asm volatile("ld.global.nc.L2::evict_last.v4.b64 {%0,%1,%2,%3}, [%4];"
                 : "=l"(x0), "=l"(x1), "=l"(x2), "=l"(x3)
                 : "l"(p));
    v0.x = __uint_as_float((unsigned int)x0);
    v0.y = __uint_as_float((unsigned int)(x0 >> 32));
    v0.z = __uint_as_float((unsigned int)x1);
    v0.w = __uint_as_float((unsigned int)(x1 >> 32));
    v1.x = __uint_as_float((unsigned int)x2);
    v1.y = __uint_as_float((unsigned int)(x2 >> 32));
    v1.z = __uint_as_float((unsigned int)x3);
    v1.w = __uint_as_float((unsigned int)(x3 >> 32));
}

// ---------------------------------------------------------------------------
// Pass 1 (tiny): arbitration ONLY. Thread j tags label[cell] with j+1 via
// atomicMax -> surviving tag = max j = last-write-wins in (b,l) row-major
// order (XLA scatter semantics). First toucher (old==0; label plane zeroed
// by the memset) counts the unique cell — warp-ballot aggregated so the hot
// g_nnz counter sees ~1.6k atomics instead of ~49k.
// ---------------------------------------------------------------------------
__global__ void __launch_bounds__(512)
tag_kernel(const int* __restrict__ idx_user,
           const int* __restrict__ item_sets,
           float* __restrict__ out) {
    int j = blockIdx.x * blockDim.x + threadIdx.x;
    if (j >= NJ) return;
    int b = j / SETLEN;
    unsigned int u    = (unsigned int)__ldg(idx_user + b);
    unsigned int it   = (unsigned int)__ldg(item_sets + j);
    unsigned int cell = u * NUM_ITEM + it;

    int old = atomicMax((int*)(out + PLANE) + cell, j + 1);

    unsigned int m = __ballot_sync(0xFFFFFFFFu, old == 0);
    if ((threadIdx.x & 31) == 0 && m) atomicAdd(&g_nnz, __popc(m));
}

// ---------------------------------------------------------------------------
// Pass 2: warp-split resolve, 8 lanes per update j (measured optimum).
//  - each lane loads 8 dims per table as ONE 32B evict-last load, then
//    butterfly shuffle-reduces within the 8-lane group.
//  - pred: stored unconditionally by lane 0 — duplicates of a cell share
//    (u, it) => identical dot, so the race writes identical bits (benign).
//  - label: lane 0 loads the tag early (independent of the embed loads);
//    the unique winner (tag == j+1) overwrites the tag with its rating.
//  - global thread 0 emits sparsity and restores g_nnz = 0.
// ---------------------------------------------------------------------------
__global__ void __launch_bounds__(256)
resolve_kernel(const int*   __restrict__ idx_user,
               const int*   __restrict__ item_sets,
               const float* __restrict__ ratings,
               const float* __restrict__ embed_user,
               const float* __restrict__ embed_item,
               float* __restrict__ out) {
    int t = blockIdx.x * blockDim.x + threadIdx.x;
    if (t == 0) {
        out[2 * PLANE] = (float)((double)PLANE / (double)g_nnz);
        g_nnz = 0u;                              // self-cleaning invariant
    }
    int j = t >> 3;                              // update index
    int r = t & (LPJ - 1);                       // lane within 8-group
    if (j >= NJ) return;

    int b = j / SETLEN;
    unsigned int u    = (unsigned int)__ldg(idx_user + b);
    unsigned int it   = (unsigned int)__ldg(item_sets + j);
    unsigned int cell = u * NUM_ITEM + it;

    // Lane 0 issues the scattered tag + rating loads up front, overlapped
    // with everyone's embed loads (all independent addresses).
    int   tag = 0;
    float rat = 0.f;
    if (r == 0) {
        tag = ((const int*)(out + PLANE))[cell];
        rat = __ldg(ratings + j);
    }

    // Each lane: 8 dims = one 32B evict-last load per table, 8 FMAs.
    const float4* ur = (const float4*)(embed_user + (size_t)u  * NUM_HIDDEN);
    const float4* ir = (const float4*)(embed_item + (size_t)it * NUM_HIDDEN);
    float4 a0, a1, c0, c1;
    ldg32B_evict_last(ur + 2*r, a0, a1);
    ldg32B_evict_last(ir + 2*r, c0, c1);
    float s  = fmaf(a0.x,c0.x, fmaf(a0.y,c0.y, fmaf(a0.z,c0.z, a0.w*c0.w)));
    s       += fmaf(a1.x,c1.x, fmaf(a1.y,c1.y, fmaf(a1.z,c1.z, a1.w*c1.w)));

    // Butterfly reduce within the 8-lane group.
    s += __shfl_xor_sync(0xFFFFFFFFu, s, 4, LPJ);
    s += __shfl_xor_sync(0xFFFFFFFFu, s, 2, LPJ);
    s += __shfl_xor_sync(0xFFFFFFFFu, s, 1, LPJ);

    if (r == 0) {
        out[cell] = s;                           // pred: benign identical race
        if (tag == j + 1)
            out[PLANE + cell] = rat;             // label: unique winner
    }
}

// ---------------------------------------------------------------------------
// 3-node pipeline (structure proven across R5/R13 overlap attempts and
// R2/R4/R12 fill attempts): 512MB memset (HBM floor, ~80us) -> arbitration
// pass -> 8-lane warp-split resolve with L2-persistent embed loads.
// ---------------------------------------------------------------------------
extern "C" void kernel_launch(void* const* d_in, const int* in_sizes, int n_in,
                              void* d_out, int out_size) {
    const int*   idx_user   = (const int*)  d_in[0];
    const int*   item_sets  = (const int*)  d_in[1];
    const float* rating     = (const float*)d_in[2];
    const float* embed_user = (const float*)d_in[3];
    const float* embed_item = (const float*)d_in[4];
    float* out = (float*)d_out;

    cudaMemsetAsync(out, 0, 2ull * PLANE * sizeof(float), 0);
    tag_kernel    <<<(NJ + 511) / 512, 512>>>(idx_user, item_sets, out);
    resolve_kernel<<<(NJ * LPJ + 255) / 256, 256>>>(idx_user, item_sets, rating,
                                                    embed_user, embed_item, out);
}